// round 1
// baseline (speedup 1.0000x reference)
#include <cuda_runtime.h>

// Resize_38104949850218: trilinear resize [4,128,128,128,2] -> [4,192,192,192,2]
// Fused single-pass gather: one thread per output (b,i,j,k), both channels as float2.

#define IN_S   128
#define OUT_S  192
#define BATCH  4
#define TOTAL  (BATCH * OUT_S * OUT_S * OUT_S)   // 28,311,552 output voxel-pairs

// Matches neurite/jax reference math exactly:
//   loc  = o / 1.5  (fp32 IEEE divide)
//   cloc = clip(loc, 0, 127)
//   i0   = clip(floor(loc), 0, 127); i1 = min(i0+1, 127)
//   w0   = i1 - cloc; w1 = 1 - w0
__device__ __forceinline__ void axis_weights(int o, int& i0, int& i1,
                                             float& w0, float& w1) {
    float loc  = __fdiv_rn((float)o, 1.5f);          // IEEE RN, matches XLA
    float cloc = fminf(loc, 127.0f);                 // loc >= 0 always
    int   f    = (int)floorf(loc);
    i0 = (f < 127) ? f : 127;
    i1 = (i0 < 127) ? (i0 + 1) : 127;
    w0 = (float)i1 - cloc;
    w1 = 1.0f - w0;
}

__global__ void __launch_bounds__(256)
resize_trilinear_kernel(const float2* __restrict__ in, float2* __restrict__ out) {
    int tid = blockIdx.x * blockDim.x + threadIdx.x;
    if (tid >= TOTAL) return;

    int k = tid % OUT_S;             // axis-3 (W) fastest -> coalesced
    int r = tid / OUT_S;
    int j = r % OUT_S;               // axis-2 (H)
    r /= OUT_S;
    int i = r % OUT_S;               // axis-1 (D)
    int b = r / OUT_S;

    int d0, d1, h0, h1, w0i, w1i;
    float wd0, wd1, wh0, wh1, ww0, ww1;
    axis_weights(i, d0, d1, wd0, wd1);
    axis_weights(j, h0, h1, wh0, wh1);
    axis_weights(k, w0i, w1i, ww0, ww1);

    const float2* p = in + (size_t)b * (IN_S * IN_S * IN_S);

    int r00 = (d0 * IN_S + h0) * IN_S;
    int r01 = (d0 * IN_S + h1) * IN_S;
    int r10 = (d1 * IN_S + h0) * IN_S;
    int r11 = (d1 * IN_S + h1) * IN_S;

    // 8 corners (each float2 = 2 channels)
    float2 v000 = __ldg(p + r00 + w0i);   // d0 h0 w0
    float2 v100 = __ldg(p + r10 + w0i);   // d1 h0 w0
    float2 v010 = __ldg(p + r01 + w0i);   // d0 h1 w0
    float2 v110 = __ldg(p + r11 + w0i);   // d1 h1 w0
    float2 v001 = __ldg(p + r00 + w1i);   // d0 h0 w1
    float2 v101 = __ldg(p + r10 + w1i);   // d1 h0 w1
    float2 v011 = __ldg(p + r01 + w1i);   // d0 h1 w1
    float2 v111 = __ldg(p + r11 + w1i);   // d1 h1 w1

    // Reference nesting: interp axis-1 (d) innermost, then axis-2 (h), then axis-3 (w)
    float2 res;
    {
        // channel x
        float th0w0 = wd0 * v000.x + wd1 * v100.x;
        float th1w0 = wd0 * v010.x + wd1 * v110.x;
        float th0w1 = wd0 * v001.x + wd1 * v101.x;
        float th1w1 = wd0 * v011.x + wd1 * v111.x;
        float tw0   = wh0 * th0w0 + wh1 * th1w0;
        float tw1   = wh0 * th0w1 + wh1 * th1w1;
        res.x = ww0 * tw0 + ww1 * tw1;
        // channel y
        float uh0w0 = wd0 * v000.y + wd1 * v100.y;
        float uh1w0 = wd0 * v010.y + wd1 * v110.y;
        float uh0w1 = wd0 * v001.y + wd1 * v101.y;
        float uh1w1 = wd0 * v011.y + wd1 * v111.y;
        float uw0   = wh0 * uh0w0 + wh1 * uh1w0;
        float uw1   = wh0 * uh0w1 + wh1 * uh1w1;
        res.y = ww0 * uw0 + ww1 * uw1;
    }

    out[tid] = res;
}

extern "C" void kernel_launch(void* const* d_in, const int* in_sizes, int n_in,
                              void* d_out, int out_size) {
    const float2* in  = (const float2*)d_in[0];
    float2*       out = (float2*)d_out;
    const int threads = 256;
    const int blocks  = (TOTAL + threads - 1) / threads;  // 110,592
    resize_trilinear_kernel<<<blocks, threads>>>(in, out);
}

// round 2
// speedup vs baseline: 2.1913x; 2.1913x over previous
#include <cuda_runtime.h>

// Resize_38104949850218: trilinear resize [4,128,128,128,2] -> [4,192,192,192,2]
// zoom = 1.5 per axis: output phase repeats every 3 outputs <-> 2 inputs.
// One thread produces 3 consecutive k-outputs (one period) for one (b,i,j):
//   k = 3m..3m+2 needs input w in {2m, 2m+1, 2m+2(clipped)}.
// Loads: 4 corner rows x (float4 @ w=2m + float2 @ w=2m+2) = 8 loads / 3 outputs.
// Stores staged via smem -> 2 coalesced STG.128 per warp.

#define IN_S   128
#define OUT_S  192

static constexpr float INV15 = 1.0f / 1.5f;   // 0x3F2AAAAB

// Reference weight math: loc = o/1.5; cloc=clip(loc,0,127);
// i0=clip(floor(loc),0,127); i1=min(i0+1,127); w0=i1-cloc; w1=1-w0.
// (o*INV15 differs from o/1.5 by <=1 ulp; exact for o multiple of 3.)
__device__ __forceinline__ void axis_w(int o, int& i0, int& i1, float& w0, float& w1) {
    float loc = (float)o * INV15;
    float cl  = fminf(loc, 127.0f);
    int f = (int)loc;                 // loc >= 0 -> trunc == floor
    i0 = (f < 127) ? f : 127;
    i1 = (i0 < 127) ? (i0 + 1) : 127;
    w0 = (float)i1 - cl;
    w1 = 1.0f - w0;
}

__global__ void __launch_bounds__(256)
resize_period_kernel(const float4* __restrict__ in4,
                     const float2* __restrict__ in2,
                     float4* __restrict__ out4) {
    __shared__ float sbuf[8 * 192];          // 8 warps x 768B staging

    const int tx = threadIdx.x;              // m in [0,64)
    const int ty = threadIdx.y;              // j sub-index
    const int m  = tx;
    const int j  = blockIdx.x * 4 + ty;
    const int i  = blockIdx.y;
    const int b  = blockIdx.z;

    // ---- warp-uniform d/h weights ----
    int d0, d1, h0, h1;
    float wd0, wd1, wh0, wh1;
    axis_w(i, d0, d1, wd0, wd1);
    axis_w(j, h0, h1, wh0, wh1);

    // ---- per-lane w-phase weights (k = 3m, 3m+1, 3m+2) ----
    // phase 0: loc = 2m exact -> w0=1 -> out = u0
    float loca = (float)(3 * m + 1) * INV15;          // <= 126.67, no clip
    float w0a  = (float)(2 * m + 1) - loca;
    float w1a  = 1.0f - w0a;
    float locb = fminf((float)(3 * m + 2) * INV15, 127.0f);
    int   i1b  = min(2 * m + 2, 127);
    float w0b  = (float)i1b - locb;
    float w1b  = 1.0f - w0b;

    // ---- gather 4 corner rows ----
    const float4* p4 = in4 + (size_t)b * (IN_S * IN_S * (IN_S / 2)); // 128*128*64 float4
    const float2* p2 = in2 + (size_t)b * (IN_S * IN_S * IN_S);

    int r00 = (d0 * IN_S + h0) * (IN_S / 2);   // float4 row bases (row = 64 float4)
    int r01 = (d0 * IN_S + h1) * (IN_S / 2);
    int r10 = (d1 * IN_S + h0) * (IN_S / 2);
    int r11 = (d1 * IN_S + h1) * (IN_S / 2);
    int w2  = min(2 * m + 2, 127);

    float4 A00 = __ldg(p4 + r00 + m);          // w=2m (.x,.y) and w=2m+1 (.z,.w)
    float4 A01 = __ldg(p4 + r01 + m);
    float4 A10 = __ldg(p4 + r10 + m);
    float4 A11 = __ldg(p4 + r11 + m);
    float2 B00 = __ldg(p2 + r00 * 2 + w2);     // w=2m+2 (clipped)
    float2 B01 = __ldg(p2 + r01 * 2 + w2);
    float2 B10 = __ldg(p2 + r10 * 2 + w2);
    float2 B11 = __ldg(p2 + r11 * 2 + w2);

    // ---- d-interp (axis 1), then h-interp (axis 2) -> u[w-pos], 2 channels ----
    float t0h0x = wd0 * A00.x + wd1 * A10.x, t0h0y = wd0 * A00.y + wd1 * A10.y;
    float t1h0x = wd0 * A00.z + wd1 * A10.z, t1h0y = wd0 * A00.w + wd1 * A10.w;
    float t2h0x = wd0 * B00.x + wd1 * B10.x, t2h0y = wd0 * B00.y + wd1 * B10.y;
    float t0h1x = wd0 * A01.x + wd1 * A11.x, t0h1y = wd0 * A01.y + wd1 * A11.y;
    float t1h1x = wd0 * A01.z + wd1 * A11.z, t1h1y = wd0 * A01.w + wd1 * A11.w;
    float t2h1x = wd0 * B01.x + wd1 * B11.x, t2h1y = wd0 * B01.y + wd1 * B11.y;

    float u0x = wh0 * t0h0x + wh1 * t0h1x, u0y = wh0 * t0h0y + wh1 * t0h1y;
    float u1x = wh0 * t1h0x + wh1 * t1h1x, u1y = wh0 * t1h0y + wh1 * t1h1y;
    float u2x = wh0 * t2h0x + wh1 * t2h1x, u2y = wh0 * t2h0y + wh1 * t2h1y;

    // ---- w-interp (axis 3): 3 outputs ----
    float2 o0 = make_float2(u0x, u0y);                              // w0=1 exact
    float2 o1 = make_float2(w0a * u0x + w1a * u1x, w0a * u0y + w1a * u1y);
    float2 o2 = make_float2(w0b * u1x + w1b * u2x, w0b * u1y + w1b * u2y);

    // ---- stage per-warp 768B chunk in smem, emit coalesced STG.128 ----
    const int half = tx >> 5;                  // 0: k 0..95, 1: k 96..191
    const int lane = tx & 31;
    const int warp = (ty << 1) | half;
    float2* srow = (float2*)(sbuf + warp * 192);
    srow[lane * 3 + 0] = o0;
    srow[lane * 3 + 1] = o1;
    srow[lane * 3 + 2] = o2;
    __syncwarp();

    const float4* srow4 = (const float4*)(sbuf + warp * 192);   // 48 float4
    int base4 = ((b * OUT_S + i) * OUT_S + j) * (OUT_S / 2) + half * 48;
    out4[base4 + lane] = srow4[lane];
    if (lane < 16) out4[base4 + 32 + lane] = srow4[32 + lane];
}

extern "C" void kernel_launch(void* const* d_in, const int* in_sizes, int n_in,
                              void* d_out, int out_size) {
    const float4* in4 = (const float4*)d_in[0];
    const float2* in2 = (const float2*)d_in[0];
    float4*       out = (float4*)d_out;
    dim3 block(64, 4);                 // 256 threads: 64 periods x 4 j-rows
    dim3 grid(OUT_S / 4, OUT_S, 4);    // (48, 192, 4)
    resize_period_kernel<<<grid, block>>>(in4, in2, out);
}

// round 3
// speedup vs baseline: 2.6570x; 1.2125x over previous
#include <cuda_runtime.h>

// Trilinear resize [4,128,128,128,2] -> [4,192,192,192,2], zoom 1.5/axis.
// 3x3 (j,k) output tile per thread: j-period n covers j=3n..3n+2 from input
// h rows {2n,2n+1,2n+2}; k-period m covers k=3m..3m+2 from w {2m,2m+1,2m+2}.
// Loads: 6 rows x (LDG.128 + LDG.64) = 12 loads / 9 outputs.

#define IN_S   128
#define OUT_S  192

static constexpr float INV15 = 1.0f / 1.5f;

// Reference: loc=o/1.5; cloc=clip(loc,0,127); i0=clip(floor,0,127);
// i1=min(i0+1,127); w0=i1-cloc.
__device__ __forceinline__ void axis_w(int o, int& i0, int& i1, float& w0, float& w1) {
    float loc = (float)o * INV15;
    float cl  = fminf(loc, 127.0f);
    int f = (int)loc;
    i0 = (f < 127) ? f : 127;
    i1 = (i0 < 127) ? (i0 + 1) : 127;
    w0 = (float)i1 - cl;
    w1 = 1.0f - w0;
}

__device__ __forceinline__ float2 lerp2(float w0, float2 a, float w1, float2 b) {
    return make_float2(w0 * a.x + w1 * b.x, w0 * a.y + w1 * b.y);
}

__global__ void __launch_bounds__(128)
resize_tile33_kernel(const float4* __restrict__ in4,
                     const float2* __restrict__ in2,
                     float4* __restrict__ out4) {
    __shared__ float sbuf[4][3][192];        // 4 warps x 3 j-rows x 768B

    const int tx   = threadIdx.x;            // k-period m in [0,64)
    const int ty   = threadIdx.y;            // j-period sub-index (0..1)
    const int m    = tx;
    const int half = tx >> 5;
    const int lane = tx & 31;
    const int warp = (ty << 1) | half;

    const int n = blockIdx.x * 2 + ty;       // j-period in [0,64)
    const int i = blockIdx.y;
    const int b = blockIdx.z;

    // ---- d weights (warp-uniform) ----
    int d0, d1; float wd0, wd1;
    axis_w(i, d0, d1, wd0, wd1);

    // ---- h rows + j weights (warp-uniform) ----
    const int h0r = 2 * n;
    const int h1r = 2 * n + 1;
    const int h2r = min(2 * n + 2, 127);
    float loc1 = (float)(3 * n + 1) * INV15;              // < 127
    float wj1_0 = (float)(2 * n + 1) - loc1;
    float wj1_1 = 1.0f - wj1_0;
    float loc2 = fminf((float)(3 * n + 2) * INV15, 127.0f);
    float wj2_0 = (float)h2r - loc2;                       // i1 = h2r
    float wj2_1 = 1.0f - wj2_0;

    // ---- k phase weights (per lane) ----
    float loca = (float)(3 * m + 1) * INV15;
    float wk1_0 = (float)(2 * m + 1) - loca;
    float wk1_1 = 1.0f - wk1_0;
    int   w2   = min(2 * m + 2, 127);
    float locb = fminf((float)(3 * m + 2) * INV15, 127.0f);
    float wk2_0 = (float)w2 - locb;
    float wk2_1 = 1.0f - wk2_0;

    // ---- gather: 6 rows x (f4 @ w=2m, f2 @ w=w2) ----
    const float4* p4 = in4 + (size_t)b * (IN_S * IN_S * (IN_S / 2));
    const float2* p2 = in2 + (size_t)b * (IN_S * IN_S * IN_S);

    int rA0 = (d0 * IN_S + h0r) * (IN_S / 2);
    int rA1 = (d0 * IN_S + h1r) * (IN_S / 2);
    int rA2 = (d0 * IN_S + h2r) * (IN_S / 2);
    int rB0 = (d1 * IN_S + h0r) * (IN_S / 2);
    int rB1 = (d1 * IN_S + h1r) * (IN_S / 2);
    int rB2 = (d1 * IN_S + h2r) * (IN_S / 2);

    float4 A0 = __ldg(p4 + rA0 + m);
    float4 A1 = __ldg(p4 + rA1 + m);
    float4 A2 = __ldg(p4 + rA2 + m);
    float4 C0 = __ldg(p4 + rB0 + m);
    float4 C1 = __ldg(p4 + rB1 + m);
    float4 C2 = __ldg(p4 + rB2 + m);
    float2 E0 = __ldg(p2 + rA0 * 2 + w2);
    float2 E1 = __ldg(p2 + rA1 * 2 + w2);
    float2 E2 = __ldg(p2 + rA2 * 2 + w2);
    float2 F0 = __ldg(p2 + rB0 * 2 + w2);
    float2 F1 = __ldg(p2 + rB1 * 2 + w2);
    float2 F2 = __ldg(p2 + rB2 * 2 + w2);

    // ---- d-interp: t[h][wpos] as float2 (2 channels); wpos 0..2 ----
    float2 t00 = lerp2(wd0, make_float2(A0.x, A0.y), wd1, make_float2(C0.x, C0.y));
    float2 t01 = lerp2(wd0, make_float2(A0.z, A0.w), wd1, make_float2(C0.z, C0.w));
    float2 t02 = lerp2(wd0, E0, wd1, F0);
    float2 t10 = lerp2(wd0, make_float2(A1.x, A1.y), wd1, make_float2(C1.x, C1.y));
    float2 t11 = lerp2(wd0, make_float2(A1.z, A1.w), wd1, make_float2(C1.z, C1.w));
    float2 t12 = lerp2(wd0, E1, wd1, F1);
    float2 t20 = lerp2(wd0, make_float2(A2.x, A2.y), wd1, make_float2(C2.x, C2.y));
    float2 t21 = lerp2(wd0, make_float2(A2.z, A2.w), wd1, make_float2(C2.z, C2.w));
    float2 t22 = lerp2(wd0, E2, wd1, F2);

    // ---- per output j-row: h-interp then k-interp, stage to smem ----
    {
        float2* s = (float2*)sbuf[warp][0];                // j = 3n (row0 exact)
        s[lane * 3 + 0] = t00;
        s[lane * 3 + 1] = lerp2(wk1_0, t00, wk1_1, t01);
        s[lane * 3 + 2] = lerp2(wk2_0, t01, wk2_1, t02);
    }
    {
        float2 u0 = lerp2(wj1_0, t00, wj1_1, t10);
        float2 u1 = lerp2(wj1_0, t01, wj1_1, t11);
        float2 u2 = lerp2(wj1_0, t02, wj1_1, t12);
        float2* s = (float2*)sbuf[warp][1];                // j = 3n+1
        s[lane * 3 + 0] = u0;
        s[lane * 3 + 1] = lerp2(wk1_0, u0, wk1_1, u1);
        s[lane * 3 + 2] = lerp2(wk2_0, u1, wk2_1, u2);
    }
    {
        float2 u0 = lerp2(wj2_0, t10, wj2_1, t20);
        float2 u1 = lerp2(wj2_0, t11, wj2_1, t21);
        float2 u2 = lerp2(wj2_0, t12, wj2_1, t22);
        float2* s = (float2*)sbuf[warp][2];                // j = 3n+2
        s[lane * 3 + 0] = u0;
        s[lane * 3 + 1] = lerp2(wk1_0, u0, wk1_1, u1);
        s[lane * 3 + 2] = lerp2(wk2_0, u1, wk2_1, u2);
    }
    __syncwarp();

    // ---- coalesced STG.128: 3 rows x 48 float4 per warp ----
    #pragma unroll
    for (int r = 0; r < 3; r++) {
        const float4* s4 = (const float4*)sbuf[warp][r];
        int jrow = 3 * n + r;
        int base4 = ((b * OUT_S + i) * OUT_S + jrow) * (OUT_S / 2) + half * 48;
        out4[base4 + lane] = s4[lane];
        if (lane < 16) out4[base4 + 32 + lane] = s4[32 + lane];
    }
}

extern "C" void kernel_launch(void* const* d_in, const int* in_sizes, int n_in,
                              void* d_out, int out_size) {
    const float4* in4 = (const float4*)d_in[0];
    const float2* in2 = (const float2*)d_in[0];
    float4*       out = (float4*)d_out;
    dim3 block(64, 2);                  // 128 threads: 64 k-periods x 2 j-periods
    dim3 grid(OUT_S / 6, OUT_S, 4);     // (32, 192, 4)
    resize_tile33_kernel<<<grid, block>>>(in4, in2, out);
}